// round 17
// baseline (speedup 1.0000x reference)
#include <cuda_runtime.h>
#include <math.h>

#define NN 50000
#define EE 800000
#define FIN 32
#define FOUT 64
#define CIN 160    // 5 blocks of 32
#define COUT 128   // 2 gates x 64

#define GRID 148
#define BLOCK 1024
#define TOT (GRID * BLOCK)
#define NWARPS (TOT / 32)
#define RNG ((NN + GRID - 1) / GRID)   // 338 nodes per block for scan

typedef unsigned long long ull;

// ---------------- scratch (device globals; no allocation) ----------------
__device__ float g_degin[NN], g_degout[NN];
__device__ float g_rdegin[NN], g_rdegout[NN];
__device__ int   g_cntin[NN], g_cntout[NN], g_fill[NN];
__device__ int   g_instart[NN + 1], g_outstart[NN + 1];
__device__ int   g_psum_in[GRID], g_psum_out[GRID];
__device__ int   g_poff_in[GRID], g_poff_out[GRID];
__device__ int   g_bucket[EE];
__device__ __align__(16) int2 g_fwd_pack[EE];  // (src, rdegout[src]) in CSC order
__device__ __align__(16) int2 g_rev_pack[EE];  // (dst[j], ci[j]) in edge-id order
__device__ int   g_T;   // # edges whose int32 key (dst*N+src) overflows negative
__device__ __align__(16) float g_Y1o[NN * FIN];
__device__ __align__(16) float g_Y1i[NN * FIN];
__device__ __align__(16) float g_U2o[NN * FIN];
__device__ __align__(16) float g_U2i[NN * FIN];
__device__ __align__(16) float g_Wc[CIN * COUT];
__device__ float g_bc[COUT];

// barrier state (sense-reversing; returns to count=0 each use, sense wraps)
__device__ unsigned g_bar_count = 0u;
__device__ unsigned g_bar_sense = 0u;

// ---------------- f32x2 helpers ----------------
__device__ __forceinline__ void fma2(ull& d, ull a, ull b) {
    asm("fma.rn.f32x2 %0, %1, %2, %3;" : "=l"(d) : "l"(a), "l"(b), "l"(d));
}
__device__ __forceinline__ ull bcast2(float x) {
    ull r; asm("mov.b64 %0, {%1, %1};" : "=l"(r) : "f"(x)); return r;
}
__device__ __forceinline__ float2 unpack2(ull v) {
    float2 f; asm("mov.b64 {%0, %1}, %2;" : "=f"(f.x), "=f"(f.y) : "l"(v)); return f;
}

// ---------------- grid barrier with release + L1D invalidate ----------------
// __threadfence() (gpu scope) emits CCTL.IVALL on sm_103a -> flushes this SM's
// L1D, giving kernel-boundary-equivalent visibility for cross-block data.
__device__ __forceinline__ void grid_barrier() {
    __syncthreads();
    if (threadIdx.x == 0) {
        __threadfence();                       // publish this block's writes
        unsigned gen = atomicAdd(&g_bar_sense, 0u);
        unsigned a = atomicAdd(&g_bar_count, 1u);
        if (a == GRID - 1) {
            g_bar_count = 0u;
            __threadfence();
            atomicAdd(&g_bar_sense, 1u);
        } else {
            while (atomicAdd(&g_bar_sense, 0u) == gen) { }
        }
        __threadfence();                       // acquire + L1D invalidate
    }
    __syncthreads();
}

// exclusive scan over the block's 1024 per-thread values (all threads call)
__device__ __forceinline__ int block_excl_scan(int v, int* swork) {
    int lane = threadIdx.x & 31, wid = threadIdx.x >> 5;
    int x = v;
#pragma unroll
    for (int o = 1; o < 32; o <<= 1) {
        int t = __shfl_up_sync(0xffffffffu, x, o);
        if (lane >= o) x += t;
    }
    if (lane == 31) swork[wid] = x;
    __syncthreads();
    if (wid == 0) {
        int ws = swork[lane];
#pragma unroll
        for (int o = 1; o < 32; o <<= 1) {
            int t = __shfl_up_sync(0xffffffffu, ws, o);
            if (lane >= o) ws += t;
        }
        swork[lane] = ws;
    }
    __syncthreads();
    int r = x - v + (wid ? swork[wid - 1] : 0);
    __syncthreads();
    return r;
}

// ---------------- the whole pipeline in one persistent kernel ----------------
__global__ __launch_bounds__(BLOCK, 1) void k_all(
    const float* __restrict__ X, const int* __restrict__ src,
    const int* __restrict__ dst, const float* __restrict__ ew,
    const float* __restrict__ Wz, const float* __restrict__ bz,
    const float* __restrict__ Wh, const float* __restrict__ bh,
    float* __restrict__ out)
{
    extern __shared__ float sm[];
    int* si = (int*)sm;
    int tid = threadIdx.x;
    int gtid = blockIdx.x * BLOCK + tid;
    int lane = tid & 31;

    // ---- S0: zero counters + build combined weights ----
    // H==0 so only top-32 rows of each 96-row W matter:
    //   blk0: W00+W10-W02-W12, blk1: W01, blk2: W11, blk3: 2*W02, blk4: 2*W12
    for (int i = gtid; i < NN; i += TOT) {
        g_degin[i] = 0.f; g_degout[i] = 0.f;
        g_cntin[i] = 0;   g_cntout[i] = 0;  g_fill[i] = 0;
    }
    for (int i = gtid; i < CIN * COUT; i += TOT) {
        int R = i / COUT, C = i % COUT;
        int gate = C / FOUT, c = C % FOUT;
        const float* W = gate ? Wh : Wz;  // (2,3,96,64)
        int blk = R / 32, r = R % 32;
#define WV(d, k) W[(((d) * 3 + (k)) * 96 + r) * 64 + c]
        float v;
        if (blk == 0)      v = WV(0, 0) + WV(1, 0) - WV(0, 2) - WV(1, 2);
        else if (blk == 1) v = WV(0, 1);
        else if (blk == 2) v = WV(1, 1);
        else if (blk == 3) v = 2.f * WV(0, 2);
        else               v = 2.f * WV(1, 2);
#undef WV
        g_Wc[i] = v;
        if (R == 0) g_bc[C] = gate ? bh[c] : bz[c];
    }
    if (gtid == 0) g_T = 0;
    grid_barrier();

    // ---- S1: histogram (+ overflow-key count) ----
    // Reference argsort keys dst*N+src are int32 (JAX x64 off): keys >= 2^31
    // wrap negative and sort FIRST (rotation). Count them into g_T.
    {
        int nit = (EE + TOT - 1) / TOT;
        for (int it = 0; it < nit; it++) {
            int j = gtid + it * TOT;
            bool valid = j < EE;
            int s = valid ? src[j] : -1;
            int d = valid ? dst[j] : 0;
            float ww = valid ? ew[j] : 0.f;
            if (valid) {
                atomicAdd(&g_cntin[d], 1);
                atomicAdd(&g_degin[d], ww);
            }
            // src sorted -> equal-src runs contiguous; warp-segmented reduce
            int sprev = __shfl_up_sync(0xffffffffu, s, 1);
            bool bound = (lane == 0) || (s != sprev);
            unsigned bmask = __ballot_sync(0xffffffffu, bound);
            float x = ww;
#pragma unroll
            for (int o = 1; o < 32; o <<= 1) {
                float t = __shfl_down_sync(0xffffffffu, x, o);
                int sd  = __shfl_down_sync(0xffffffffu, s, o);
                if (lane + o < 32 && sd == s) x += t;
            }
            if (bound && valid) {
                unsigned rest = (lane == 31) ? 0u : (bmask & ~((2u << lane) - 1u));
                int next = rest ? (__ffs(rest) - 1) : 32;
                atomicAdd(&g_degout[s], x);
                atomicAdd(&g_cntout[s], next - lane);
            }
            bool hi = valid &&
                (((long long)d * (long long)NN + (long long)s) >= 2147483648LL);
            unsigned m = __ballot_sync(0xffffffffu, hi);
            if (lane == 0 && m) atomicAdd(&g_T, __popc(m));
        }
    }
    grid_barrier();

    // ---- S2a: per-block partial sums over node range ----
    {
        int rb = blockIdx.x * RNG;
        int re = rb + RNG; if (re > NN) re = NN;
        int sin = 0, sout = 0;
        for (int i = rb + tid; i < re; i += BLOCK) {
            sin += g_cntin[i]; sout += g_cntout[i];
        }
        int ein = block_excl_scan(sin, si);
        if (tid == BLOCK - 1) g_psum_in[blockIdx.x] = ein + sin;
        int eout = block_excl_scan(sout, si);
        if (tid == BLOCK - 1) g_psum_out[blockIdx.x] = eout + sout;
    }
    grid_barrier();

    // ---- S2b: block 0 scans the 148 partials ----
    if (blockIdx.x == 0) {
        int v = (tid < GRID) ? g_psum_in[tid] : 0;
        int e = block_excl_scan(v, si);
        if (tid < GRID) g_poff_in[tid] = e;
        v = (tid < GRID) ? g_psum_out[tid] : 0;
        e = block_excl_scan(v, si);
        if (tid < GRID) g_poff_out[tid] = e;
        if (tid == 0) { g_instart[NN] = EE; g_outstart[NN] = EE; }
    }
    grid_barrier();

    // ---- S2c: local exclusive scan + reciprocals ----
    {
        int rb = blockIdx.x * RNG;
        int i = rb + tid;
        bool valid = (tid < RNG) && (i < NN);
        int v = valid ? g_cntin[i] : 0;
        int e = block_excl_scan(v, si) + g_poff_in[blockIdx.x];
        if (valid) g_instart[i] = e;
        v = valid ? g_cntout[i] : 0;
        e = block_excl_scan(v, si) + g_poff_out[blockIdx.x];
        if (valid) g_outstart[i] = e;
        if (valid) {
            g_rdegin[i]  = 1.0f / g_degin[i];   // exact same op as reference
            g_rdegout[i] = 1.0f / g_degout[i];
        }
    }
    grid_barrier();

    // ---- S3: bucket fill ----
    for (int j = gtid; j < EE; j += TOT) {
        int d = dst[j];
        int t = atomicAdd(&g_fill[d], 1);
        g_bucket[g_instart[d] + t] = j;
    }
    grid_barrier();

    // ---- S4: per-dst insertion sort (stable rank by edge id == by src) ----
    for (int i = gtid; i < NN; i += TOT) {
        int b = g_instart[i], e = g_instart[i + 1];
        for (int p = b + 1; p < e; p++) {
            int v = g_bucket[p];
            int q = p - 1;
            while (q >= b && g_bucket[q] > v) { g_bucket[q + 1] = g_bucket[q]; q--; }
            g_bucket[q + 1] = v;
        }
    }
    grid_barrier();

    // ---- S5: edge-parallel fill of packed arrays ----
    // Rank t is the pure (dst,src) rank; reference order is a ROTATION (the T
    // overflow-key edges first): rank t sits at ref position (t+T) mod E, and
    // its reverse coefficient is norm_in at that POSITION = 1/deg_in[src[...]].
    {
        int T = g_T;
        for (int t = gtid; t < EE; t += TOT) {
            int j = g_bucket[t];
            int s = src[j];
            g_fwd_pack[t] = make_int2(s, __float_as_int(g_rdegout[s]));
            int tref = t + T; if (tref >= EE) tref -= EE;
            g_rev_pack[j] = make_int2(dst[j], __float_as_int(g_rdegin[src[tref]]));
        }
    }
    grid_barrier();

    // ---- S6 + S7: propagation (two chebyshev hops) ----
    // Warp = one node; 4 groups of 8 lanes gather different neighbor rows as
    // float4 (8 lanes x 16B = 128B row); cross-group shfl reduce at the end.
    {
        int warpId = gtid >> 5;
        int g = lane >> 3, sub = lane & 7;
#pragma unroll
        for (int phase = 0; phase < 2; phase++) {
            const float4* __restrict__ inF = (const float4*)(phase ? g_Y1o : X);
            const float4* __restrict__ inR = (const float4*)(phase ? g_Y1i : X);
            float4* outF = (float4*)(phase ? g_U2o : g_Y1o);
            float4* outR = (float4*)(phase ? g_U2i : g_Y1i);
            for (int i = warpId; i < NN; i += NWARPS) {
                int b  = g_instart[i],  e  = g_instart[i + 1];
                int b2 = g_outstart[i], e2 = g_outstart[i + 1];

                float4 aF = make_float4(0.f, 0.f, 0.f, 0.f);
#pragma unroll 4
                for (int t = b + g; t < e; t += 4) {
                    int2 pk = g_fwd_pack[t];
                    float c = __int_as_float(pk.y);
                    float4 v = inF[pk.x * 8 + sub];
                    aF.x += c * v.x; aF.y += c * v.y;
                    aF.z += c * v.z; aF.w += c * v.w;
                }
                float4 aR = make_float4(0.f, 0.f, 0.f, 0.f);
#pragma unroll 4
                for (int j = b2 + g; j < e2; j += 4) {
                    int2 pk = g_rev_pack[j];
                    float c = __int_as_float(pk.y);
                    float4 v = inR[pk.x * 8 + sub];
                    aR.x += c * v.x; aR.y += c * v.y;
                    aR.z += c * v.z; aR.w += c * v.w;
                }
#pragma unroll
                for (int o = 8; o <= 16; o <<= 1) {
                    aF.x += __shfl_xor_sync(0xffffffffu, aF.x, o);
                    aF.y += __shfl_xor_sync(0xffffffffu, aF.y, o);
                    aF.z += __shfl_xor_sync(0xffffffffu, aF.z, o);
                    aF.w += __shfl_xor_sync(0xffffffffu, aF.w, o);
                    aR.x += __shfl_xor_sync(0xffffffffu, aR.x, o);
                    aR.y += __shfl_xor_sync(0xffffffffu, aR.y, o);
                    aR.z += __shfl_xor_sync(0xffffffffu, aR.z, o);
                    aR.w += __shfl_xor_sync(0xffffffffu, aR.w, o);
                }
                if (g == 0) {
                    outF[i * 8 + sub] = aF;
                    outR[i * 8 + sub] = aR;
                }
            }
            grid_barrier();
        }
    }

    // ---- S8: fused GEMM + epilogue ----
    // L = [X|Y1o|Y1i|U2o|U2i] @ Wc + bc; out = sigmoid(-z) * tanh(h)
    // 128-node tiles grid-strided; tx=tid&7 (col group of 8), ty=tid>>3 (node).
    {
        float* Ws = sm;                  // [160][128] = 80KB
        float* Fs = sm + CIN * COUT;     // [128][33] padded = 16.9KB

        for (int p = tid; p < CIN * COUT / 4; p += BLOCK)
            ((float4*)Ws)[p] = ((const float4*)g_Wc)[p];

        int tx = tid & 7;
        int ty = tid >> 3;
        const int NT = (NN + 127) / 128;   // 391 tiles

        for (int tile = blockIdx.x; tile < NT; tile += GRID) {
            int nodeBase = tile * 128;
            ull az[4], ah[4];
#pragma unroll
            for (int p = 0; p < 4; p++) { az[p] = 0ull; ah[p] = 0ull; }

            for (int kc = 0; kc < 5; kc++) {
                __syncthreads();
                const float* A;
                if (kc == 0) A = X;
                else if (kc == 1) A = g_Y1o;
                else if (kc == 2) A = g_Y1i;
                else if (kc == 3) A = g_U2o;
                else A = g_U2i;
                {   // stage 128 nodes x 32 feats: exactly one float4 per thread
                    int nn = tid >> 3, kk4 = tid & 7;
                    int node = nodeBase + nn;
                    float4 v = make_float4(0.f, 0.f, 0.f, 0.f);
                    if (node < NN) v = ((const float4*)(A + (size_t)node * FIN))[kk4];
                    float* dp = &Fs[nn * 33 + kk4 * 4];
                    dp[0] = v.x; dp[1] = v.y; dp[2] = v.z; dp[3] = v.w;
                }
                __syncthreads();
#pragma unroll 8
                for (int kk = 0; kk < 32; kk++) {
                    int k = kc * 32 + kk;
                    ull f0 = bcast2(Fs[ty * 33 + kk]);
                    const ulonglong2* wz = (const ulonglong2*)&Ws[k * COUT + tx * 8];
                    const ulonglong2* wh = (const ulonglong2*)&Ws[k * COUT + 64 + tx * 8];
                    ulonglong2 z01 = wz[0], z23 = wz[1];
                    ulonglong2 h01 = wh[0], h23 = wh[1];
                    fma2(az[0], f0, z01.x); fma2(az[1], f0, z01.y);
                    fma2(az[2], f0, z23.x); fma2(az[3], f0, z23.y);
                    fma2(ah[0], f0, h01.x); fma2(ah[1], f0, h01.y);
                    fma2(ah[2], f0, h23.x); fma2(ah[3], f0, h23.y);
                }
            }

            int node = nodeBase + ty;
            if (node < NN) {
                float o[8];
#pragma unroll
                for (int p = 0; p < 4; p++) {
                    float2 z2 = unpack2(az[p]);
                    float2 h2 = unpack2(ah[p]);
                    int c = tx * 8 + p * 2;
#pragma unroll
                    for (int q = 0; q < 2; q++) {
                        float z = (q ? z2.y : z2.x) + g_bc[c + q];
                        float h = (q ? h2.y : h2.x) + g_bc[64 + c + q];
                        float sz = __fdividef(1.f, 1.f + __expf(z));  // sigmoid(-z)
                        float e2 = __expf(2.f * h);
                        float th = 1.f - __fdividef(2.f, e2 + 1.f);   // tanh(h)
                        o[p * 2 + q] = sz * th;
                    }
                }
                float4* op = (float4*)(out + (size_t)node * FOUT + tx * 8);
                op[0] = make_float4(o[0], o[1], o[2], o[3]);
                op[1] = make_float4(o[4], o[5], o[6], o[7]);
            }
            __syncthreads();   // protect Fs before next tile's staging
        }
    }
}

// ---------------- launch ----------------
extern "C" void kernel_launch(void* const* d_in, const int* in_sizes, int n_in,
                              void* d_out, int out_size) {
    const float* X  = (const float*)d_in[0];
    const int*   ei = (const int*)d_in[1];
    const float* ew = (const float*)d_in[2];
    const float* Wz = (const float*)d_in[3];
    const float* bz = (const float*)d_in[4];
    // d_in[5]=Wr, d_in[6]=br are mathematically dead (H==0)
    const float* Wh = (const float*)d_in[7];
    const float* bh = (const float*)d_in[8];
    const int* src = ei;
    const int* dst = ei + EE;
    float* out = (float*)d_out;

    (void)in_sizes; (void)n_in; (void)out_size;

    const int smemBytes = (CIN * COUT + 128 * 33) * 4;   // 96.5 KB
    cudaFuncSetAttribute(k_all, cudaFuncAttributeMaxDynamicSharedMemorySize,
                         smemBytes);

    k_all<<<GRID, BLOCK, smemBytes>>>(X, src, dst, ew, Wz, bz, Wh, bh, out);
}